// round 3
// baseline (speedup 1.0000x reference)
#include <cuda_runtime.h>
#include <cuda_bf16.h>
#include <cstdint>

#define H 128
#define MAXN 50000
#define NBUF ((size_t)MAXN * H)
#define EPW 8
#define EDGE_WARPS 8
#define EDGE_BLOCK 256
#define EDGE_SMEM (128*128*4 + EDGE_WARPS*EPW*128*4)   // 64KB W2 + 32KB h staging = 96KB

// Scratch: X1, X2 (ping-pong node features), A, B (per-node partial GEMMs)
__device__ float4 g_scratch4[4 * NBUF / 4];

__device__ __forceinline__ void atomicMaxF(float* addr, float v) {
    if (v >= 0.f) atomicMax((int*)addr, __float_as_int(v));
    else          atomicMin((unsigned int*)addr, __float_as_uint(v));
}

// Packed 2xfp32 FMA (Blackwell FFMA2): d = a*b + c elementwise on f32x2.
__device__ __forceinline__ unsigned long long ffma2(
    unsigned long long a, unsigned long long b, unsigned long long c) {
    unsigned long long d;
    asm("fma.rn.f32x2 %0, %1, %2, %3;" : "=l"(d) : "l"(a), "l"(b), "l"(c));
    return d;
}
__device__ __forceinline__ unsigned long long pack2(float lo, float hi) {
    unsigned long long p;
    asm("mov.b64 %0, {%1, %2};" : "=l"(p) : "r"(__float_as_uint(lo)), "r"(__float_as_uint(hi)));
    return p;
}
__device__ __forceinline__ float2 unpack2(unsigned long long v) {
    unsigned int lo, hi;
    asm("mov.b64 {%0, %1}, %2;" : "=r"(lo), "=r"(hi) : "l"(v));
    return make_float2(__uint_as_float(lo), __uint_as_float(hi));
}

// ---------------------------------------------------------------------------
// Node GEMM: A[n] = x[n] @ (W1a - W1b) + b1 ;  B[n] = x[n] @ W1b
// ---------------------------------------------------------------------------
__global__ void __launch_bounds__(128) node_gemm_kernel(
    const float* __restrict__ x, const float* __restrict__ W1l,
    const float* __restrict__ b1l, float* __restrict__ A, float* __restrict__ Bm,
    int nN)
{
    __shared__ float xs[32][H];
    const int c = threadIdx.x;
    const int n0 = blockIdx.x * 32;

    #pragma unroll
    for (int n = 0; n < 32; n++) {
        int node = n0 + n;
        xs[n][c] = (node < nN) ? x[(size_t)node * H + c] : 0.f;
    }
    __syncthreads();

    float accA[32], accB[32];
    const float bias = b1l[c];
    #pragma unroll
    for (int n = 0; n < 32; n++) { accA[n] = bias; accB[n] = 0.f; }

    for (int k = 0; k < H; k++) {
        const float wa = W1l[k * H + c];
        const float wb = W1l[(H + k) * H + c];
        const float wd = wa - wb;
        #pragma unroll
        for (int n = 0; n < 32; n++) {
            const float xv = xs[n][k];
            accA[n] = fmaf(xv, wd, accA[n]);
            accB[n] = fmaf(xv, wb, accB[n]);
        }
    }

    #pragma unroll
    for (int n = 0; n < 32; n++) {
        int node = n0 + n;
        if (node < nN) {
            A [(size_t)node * H + c] = accA[n];
            Bm[(size_t)node * H + c] = accB[n];
        }
    }
}

// ---------------------------------------------------------------------------
// Edge kernel (FFMA2 version): h = relu(A[dst]+B[src]); out = h@W2 + b2;
// y[dst] = max(y[dst], out). Warp does EPW=8 edges per round.
// Lane owns 4 output cols as two packed f32x2 accumulators.
// ---------------------------------------------------------------------------
__global__ void __launch_bounds__(EDGE_BLOCK) edge_kernel(
    const float* __restrict__ A, const float* __restrict__ Bm,
    const float* __restrict__ W2, const float* __restrict__ b2,
    const int* __restrict__ ei, float* __restrict__ y,
    int nE, int nN)
{
    extern __shared__ float sm[];
    float* W2s = sm;                               // [128][128]
    const int tid  = threadIdx.x;
    const int lane = tid & 31;
    const int wid  = tid >> 5;
    float* hs = sm + 128 * 128 + wid * (EPW * H);  // per-warp h staging

    for (int i = tid * 4; i < 128 * 128; i += EDGE_BLOCK * 4)
        *(float4*)(W2s + i) = *(const float4*)(W2 + i);
    __syncthreads();

    const float4 b2v = *(const float4*)(b2 + lane * 4);

    const int nwork  = nE + nN;
    const int gw     = blockIdx.x * EDGE_WARPS + wid;
    const int stride = gridDim.x * EDGE_WARPS * EPW;

    for (int base = gw * EPW; base < nwork; base += stride) {
        int sidx[EPW], didx[EPW];
        #pragma unroll
        for (int j = 0; j < EPW; j++) {
            const int e = base + j;
            if (e < nE)         { sidx[j] = ei[e]; didx[j] = ei[nE + e]; }
            else if (e < nwork) { sidx[j] = didx[j] = e - nE; }   // self loop
            else                { sidx[j] = didx[j] = -1; }
        }

        // h = relu(A[dst] + B[src]) -> per-warp smem staging
        #pragma unroll
        for (int j = 0; j < EPW; j++) {
            float4 h = make_float4(0.f, 0.f, 0.f, 0.f);
            if (didx[j] >= 0) {
                const float4 a = *(const float4*)(A  + (size_t)didx[j] * H + lane * 4);
                const float4 b = *(const float4*)(Bm + (size_t)sidx[j] * H + lane * 4);
                h.x = fmaxf(a.x + b.x, 0.f);
                h.y = fmaxf(a.y + b.y, 0.f);
                h.z = fmaxf(a.z + b.z, 0.f);
                h.w = fmaxf(a.w + b.w, 0.f);
            }
            *(float4*)(hs + j * H + lane * 4) = h;
        }
        __syncwarp();

        // acc0[j] = packed cols (4*lane+0, 4*lane+1); acc1[j] = (+2, +3)
        unsigned long long acc0[EPW], acc1[EPW];
        #pragma unroll
        for (int j = 0; j < EPW; j++) { acc0[j] = 0ULL; acc1[j] = 0ULL; }

        #pragma unroll 2
        for (int k = 0; k < H; k += 4) {
            // W2 rows k..k+3, this lane's 4 cols, as pre-packed f32x2 pairs
            const ulonglong2 w0 = *(const ulonglong2*)(W2s + (k + 0) * H + lane * 4);
            const ulonglong2 w1 = *(const ulonglong2*)(W2s + (k + 1) * H + lane * 4);
            const ulonglong2 w2r = *(const ulonglong2*)(W2s + (k + 2) * H + lane * 4);
            const ulonglong2 w3 = *(const ulonglong2*)(W2s + (k + 3) * H + lane * 4);
            #pragma unroll
            for (int j = 0; j < EPW; j++) {
                const float4 h4 = *(const float4*)(hs + j * H + k);   // broadcast
                const unsigned long long p0 = pack2(h4.x, h4.x);      // ALU pipe
                const unsigned long long p1 = pack2(h4.y, h4.y);
                const unsigned long long p2 = pack2(h4.z, h4.z);
                const unsigned long long p3 = pack2(h4.w, h4.w);
                acc0[j] = ffma2(w0.x, p0, acc0[j]);
                acc1[j] = ffma2(w0.y, p0, acc1[j]);
                acc0[j] = ffma2(w1.x, p1, acc0[j]);
                acc1[j] = ffma2(w1.y, p1, acc1[j]);
                acc0[j] = ffma2(w2r.x, p2, acc0[j]);
                acc1[j] = ffma2(w2r.y, p2, acc1[j]);
                acc0[j] = ffma2(w3.x, p3, acc0[j]);
                acc1[j] = ffma2(w3.y, p3, acc1[j]);
            }
        }
        __syncwarp();   // protect hs before next iteration's writes

        #pragma unroll
        for (int j = 0; j < EPW; j++) {
            if (didx[j] < 0) continue;
            float* yr = y + (size_t)didx[j] * H + lane * 4;
            const float4 cur = *(const float4*)yr;   // racy read: stale -> conservative skip
            const float2 r0 = unpack2(acc0[j]);
            const float2 r1 = unpack2(acc1[j]);
            const float v0 = r0.x + b2v.x;
            const float v1 = r0.y + b2v.y;
            const float v2 = r1.x + b2v.z;
            const float v3 = r1.y + b2v.w;
            if (!(cur.x >= v0)) atomicMaxF(yr + 0, v0);
            if (!(cur.y >= v1)) atomicMaxF(yr + 1, v1);
            if (!(cur.z >= v2)) atomicMaxF(yr + 2, v2);
            if (!(cur.w >= v3)) atomicMaxF(yr + 3, v3);
        }
    }
}

// ---------------------------------------------------------------------------
// Final: out[n] = x[n] @ Wf + bf   (H=128 -> D=3). Warp per node.
// ---------------------------------------------------------------------------
__global__ void __launch_bounds__(256) final_kernel(
    const float* __restrict__ x, const float* __restrict__ Wf,
    const float* __restrict__ bf, float* __restrict__ out, int nN)
{
    __shared__ float Wfs[H * 3];
    const int tid = threadIdx.x;
    for (int i = tid; i < H * 3; i += 256) Wfs[i] = Wf[i];
    __syncthreads();

    const int lane = tid & 31;
    const int node = blockIdx.x * 8 + (tid >> 5);
    if (node >= nN) return;

    const float4 xv = *(const float4*)(x + (size_t)node * H + lane * 4);
    float s0 = 0.f, s1 = 0.f, s2 = 0.f;
    const float xt[4] = {xv.x, xv.y, xv.z, xv.w};
    #pragma unroll
    for (int t = 0; t < 4; t++) {
        const int k = lane * 4 + t;
        s0 = fmaf(xt[t], Wfs[k * 3 + 0], s0);
        s1 = fmaf(xt[t], Wfs[k * 3 + 1], s1);
        s2 = fmaf(xt[t], Wfs[k * 3 + 2], s2);
    }
    #pragma unroll
    for (int off = 16; off > 0; off >>= 1) {
        s0 += __shfl_down_sync(0xFFFFFFFFu, s0, off);
        s1 += __shfl_down_sync(0xFFFFFFFFu, s1, off);
        s2 += __shfl_down_sync(0xFFFFFFFFu, s2, off);
    }
    if (lane == 0) {
        out[(size_t)node * 3 + 0] = s0 + bf[0];
        out[(size_t)node * 3 + 1] = s1 + bf[1];
        out[(size_t)node * 3 + 2] = s2 + bf[2];
    }
}

// ---------------------------------------------------------------------------
extern "C" void kernel_launch(void* const* d_in, const int* in_sizes, int n_in,
                              void* d_out, int out_size)
{
    const float*      x_in = (const float*)d_in[0];
    const int*        ei   = (const int*)d_in[1];     // int32 (JAX x64 off)
    const float*      W1   = (const float*)d_in[2];   // [L, 2H, H]
    const float*      b1   = (const float*)d_in[3];   // [L, H]
    const float*      W2   = (const float*)d_in[4];   // [L, H, H]
    const float*      b2   = (const float*)d_in[5];   // [L, H]
    const float*      Wf   = (const float*)d_in[6];   // [H, 3]
    const float*      bf   = (const float*)d_in[7];   // [3]
    float*            out  = (float*)d_out;

    const int nN = in_sizes[0] / H;          // 50000
    const int nE = in_sizes[1] / 2;          // 800000
    const int L  = in_sizes[3] / H;          // 4

    void* base = nullptr;
    cudaGetSymbolAddress(&base, g_scratch4);
    float* X1 = (float*)base;
    float* X2 = X1 + NBUF;
    float* A  = X1 + 2 * NBUF;
    float* Bm = X1 + 3 * NBUF;

    cudaFuncSetAttribute(edge_kernel, cudaFuncAttributeMaxDynamicSharedMemorySize, EDGE_SMEM);

    const int nodeBlocks = (nN + 31) / 32;
    const int edgeBlocks = 148 * 2;
    float* bufs[2] = {X1, X2};

    const float* cur = x_in;
    for (int l = 0; l < L; l++) {
        node_gemm_kernel<<<nodeBlocks, 128>>>(cur, W1 + (size_t)l * 2 * H * H,
                                              b1 + (size_t)l * H, A, Bm, nN);
        float* y = bufs[l & 1];
        cudaMemsetAsync(y, 0xFF, (size_t)nN * H * sizeof(float), 0);  // NaN init
        edge_kernel<<<edgeBlocks, EDGE_BLOCK, EDGE_SMEM>>>(
            A, Bm, W2 + (size_t)l * H * H, b2 + (size_t)l * H, ei, y, nE, nN);
        cur = y;
    }
    final_kernel<<<(nN + 7) / 8, 256>>>(cur, Wf, bf, out, nN);
}

// round 4
// speedup vs baseline: 1.1007x; 1.1007x over previous
#include <cuda_runtime.h>
#include <cuda_bf16.h>
#include <cstdint>

#define H 128
#define MAXN 50000
#define NBUF ((size_t)MAXN * H)

#define TILE_M 64
#define EDGE_BLOCK 128
#define HP 132   // padded smem pitch (words) -> conflict-free mma fragment loads
#define EDGE_SMEM ((128 * HP + TILE_M * HP + TILE_M) * 4)   // W2s + Hs + dstS ~ 99.3KB

// Scratch: X1, X2 (ping-pong node features), A, B (per-node partial GEMMs)
__device__ float4 g_scratch4[4 * NBUF / 4];

__device__ __forceinline__ void atomicMaxF(float* addr, float v) {
    if (v >= 0.f) atomicMax((int*)addr, __float_as_int(v));
    else          atomicMin((unsigned int*)addr, __float_as_uint(v));
}

__device__ __forceinline__ float tf32r(float x) {
    uint32_t u;
    asm("cvt.rna.tf32.f32 %0, %1;" : "=r"(u) : "f"(x));
    return __uint_as_float(u);
}

// ---------------------------------------------------------------------------
// Node GEMM: A[n] = x[n] @ (W1a - W1b) + b1 ;  B[n] = x[n] @ W1b   (fp32)
// ---------------------------------------------------------------------------
__global__ void __launch_bounds__(128) node_gemm_kernel(
    const float* __restrict__ x, const float* __restrict__ W1l,
    const float* __restrict__ b1l, float* __restrict__ A, float* __restrict__ Bm,
    int nN)
{
    __shared__ float xs[32][H];
    const int c = threadIdx.x;
    const int n0 = blockIdx.x * 32;

    #pragma unroll
    for (int n = 0; n < 32; n++) {
        int node = n0 + n;
        xs[n][c] = (node < nN) ? x[(size_t)node * H + c] : 0.f;
    }
    __syncthreads();

    float accA[32], accB[32];
    const float bias = b1l[c];
    #pragma unroll
    for (int n = 0; n < 32; n++) { accA[n] = bias; accB[n] = 0.f; }

    for (int k = 0; k < H; k++) {
        const float wa = W1l[k * H + c];
        const float wb = W1l[(H + k) * H + c];
        const float wd = wa - wb;
        #pragma unroll
        for (int n = 0; n < 32; n++) {
            const float xv = xs[n][k];
            accA[n] = fmaf(xv, wd, accA[n]);
            accB[n] = fmaf(xv, wb, accB[n]);
        }
    }

    #pragma unroll
    for (int n = 0; n < 32; n++) {
        int node = n0 + n;
        if (node < nN) {
            A [(size_t)node * H + c] = accA[n];
            Bm[(size_t)node * H + c] = accB[n];
        }
    }
}

// ---------------------------------------------------------------------------
// Edge kernel (tf32 tensor-core): tile of 64 edges.
//   Hs[m][k] = tf32(relu(A[dst]+B[src]));  out = Hs @ W2s (mma.sync m16n8k8)
//   y[dst] = max(y[dst], out + b2)  via racy-skip atomics.
// 4 warps tile 2(M)x2(N); warp tile M=32, N=64; K=128 in 16 k8-steps.
// ---------------------------------------------------------------------------
__global__ void __launch_bounds__(EDGE_BLOCK) edge_mma_kernel(
    const float* __restrict__ A, const float* __restrict__ Bm,
    const float* __restrict__ W2, const float* __restrict__ b2,
    const int* __restrict__ ei, float* __restrict__ y,
    int nE, int nN)
{
    extern __shared__ float sm[];
    float* W2s  = sm;                       // [128][HP]
    float* Hs   = sm + 128 * HP;            // [TILE_M][HP]
    int*   dstS = (int*)(sm + 128 * HP + TILE_M * HP);

    const int tid  = threadIdx.x;
    const int lane = tid & 31;
    const int wid  = tid >> 5;
    const int mg   = wid >> 1;      // 0..1 : M group (rows 32*mg..)
    const int ng   = wid & 1;       // 0..1 : N group (cols 64*ng..)
    const int lr   = lane >> 2;     // 0..7
    const int lc   = lane & 3;      // 0..3

    // Load W2 -> smem, tf32-rounded
    for (int i = tid; i < 128 * 32; i += EDGE_BLOCK) {
        const int k = i >> 5, j = i & 31;
        float4 w = *(const float4*)(W2 + k * H + j * 4);
        w.x = tf32r(w.x); w.y = tf32r(w.y); w.z = tf32r(w.z); w.w = tf32r(w.w);
        *(float4*)(W2s + k * HP + j * 4) = w;
    }

    // Bias pairs for my output columns
    float2 b2c[8];
    #pragma unroll
    for (int ni = 0; ni < 8; ni++) {
        const int col = 64 * ng + 8 * ni + 2 * lc;
        b2c[ni] = *(const float2*)(b2 + col);
    }
    __syncthreads();

    const int nwork  = nE + nN;
    const int ntiles = (nwork + TILE_M - 1) / TILE_M;

    for (int tile = blockIdx.x; tile < ntiles; tile += gridDim.x) {
        const int e0 = tile * TILE_M;

        // ---- build H tile: each thread = half a row (64 cols) ----
        {
            const int eL   = tid >> 1;
            const int half = tid & 1;
            const int e    = e0 + eL;
            int s = -1, d = -1;
            if (e < nE)         { s = ei[e]; d = ei[nE + e]; }
            else if (e < nwork) { s = d = e - nE; }   // self loop
            if (half == 0) dstS[eL] = d;

            float* hrow = Hs + eL * HP + half * 64;
            if (d >= 0) {
                const float4* ap = (const float4*)(A  + (size_t)d * H + half * 64);
                const float4* bp = (const float4*)(Bm + (size_t)s * H + half * 64);
                #pragma unroll
                for (int i = 0; i < 16; i++) {
                    const float4 a = ap[i], b = bp[i];
                    float4 h;
                    h.x = tf32r(fmaxf(a.x + b.x, 0.f));
                    h.y = tf32r(fmaxf(a.y + b.y, 0.f));
                    h.z = tf32r(fmaxf(a.z + b.z, 0.f));
                    h.w = tf32r(fmaxf(a.w + b.w, 0.f));
                    *(float4*)(hrow + i * 4) = h;
                }
            } else {
                #pragma unroll
                for (int i = 0; i < 16; i++)
                    *(float4*)(hrow + i * 4) = make_float4(0.f, 0.f, 0.f, 0.f);
            }
        }
        __syncthreads();

        // ---- mma: acc[mi][ni][c] over K=128 ----
        float acc[2][8][4];
        #pragma unroll
        for (int mi = 0; mi < 2; mi++)
            #pragma unroll
            for (int ni = 0; ni < 8; ni++)
                #pragma unroll
                for (int c = 0; c < 4; c++) acc[mi][ni][c] = 0.f;

        #pragma unroll
        for (int ks = 0; ks < 16; ks++) {
            const int kb = ks * 8;
            uint32_t a[2][4];
            #pragma unroll
            for (int mi = 0; mi < 2; mi++) {
                const float* ab = Hs + (32 * mg + 16 * mi + lr) * HP + kb + lc;
                a[mi][0] = __float_as_uint(ab[0]);
                a[mi][1] = __float_as_uint(ab[8 * HP]);
                a[mi][2] = __float_as_uint(ab[4]);
                a[mi][3] = __float_as_uint(ab[8 * HP + 4]);
            }
            #pragma unroll
            for (int ni = 0; ni < 8; ni++) {
                const float* bb = W2s + (kb + lc) * HP + 64 * ng + 8 * ni + lr;
                const uint32_t b0 = __float_as_uint(bb[0]);
                const uint32_t b1 = __float_as_uint(bb[4 * HP]);
                #pragma unroll
                for (int mi = 0; mi < 2; mi++) {
                    asm("mma.sync.aligned.m16n8k8.row.col.f32.tf32.tf32.f32 "
                        "{%0,%1,%2,%3}, {%4,%5,%6,%7}, {%8,%9}, {%0,%1,%2,%3};"
                        : "+f"(acc[mi][ni][0]), "+f"(acc[mi][ni][1]),
                          "+f"(acc[mi][ni][2]), "+f"(acc[mi][ni][3])
                        : "r"(a[mi][0]), "r"(a[mi][1]), "r"(a[mi][2]), "r"(a[mi][3]),
                          "r"(b0), "r"(b1));
                }
            }
        }

        // ---- output: atomicMax into y[dst] with racy skip ----
        #pragma unroll
        for (int mi = 0; mi < 2; mi++) {
            const int r0 = 32 * mg + 16 * mi + lr;
            const int d0 = dstS[r0];
            const int d1 = dstS[r0 + 8];
            #pragma unroll
            for (int ni = 0; ni < 8; ni++) {
                const int col = 64 * ng + 8 * ni + 2 * lc;
                if (d0 >= 0) {
                    float* yr = y + (size_t)d0 * H + col;
                    const float2 cur = *(const float2*)yr;
                    const float v0 = acc[mi][ni][0] + b2c[ni].x;
                    const float v1 = acc[mi][ni][1] + b2c[ni].y;
                    if (!(cur.x >= v0)) atomicMaxF(yr + 0, v0);
                    if (!(cur.y >= v1)) atomicMaxF(yr + 1, v1);
                }
                if (d1 >= 0) {
                    float* yr = y + (size_t)d1 * H + col;
                    const float2 cur = *(const float2*)yr;
                    const float v2 = acc[mi][ni][2] + b2c[ni].x;
                    const float v3 = acc[mi][ni][3] + b2c[ni].y;
                    if (!(cur.x >= v2)) atomicMaxF(yr + 0, v2);
                    if (!(cur.y >= v3)) atomicMaxF(yr + 1, v3);
                }
            }
        }
        __syncthreads();   // Hs/dstS stable until all warps finish this tile
    }
}

// ---------------------------------------------------------------------------
// Final: out[n] = x[n] @ Wf + bf   (H=128 -> D=3). Warp per node.
// ---------------------------------------------------------------------------
__global__ void __launch_bounds__(256) final_kernel(
    const float* __restrict__ x, const float* __restrict__ Wf,
    const float* __restrict__ bf, float* __restrict__ out, int nN)
{
    __shared__ float Wfs[H * 3];
    const int tid = threadIdx.x;
    for (int i = tid; i < H * 3; i += 256) Wfs[i] = Wf[i];
    __syncthreads();

    const int lane = tid & 31;
    const int node = blockIdx.x * 8 + (tid >> 5);
    if (node >= nN) return;

    const float4 xv = *(const float4*)(x + (size_t)node * H + lane * 4);
    float s0 = 0.f, s1 = 0.f, s2 = 0.f;
    const float xt[4] = {xv.x, xv.y, xv.z, xv.w};
    #pragma unroll
    for (int t = 0; t < 4; t++) {
        const int k = lane * 4 + t;
        s0 = fmaf(xt[t], Wfs[k * 3 + 0], s0);
        s1 = fmaf(xt[t], Wfs[k * 3 + 1], s1);
        s2 = fmaf(xt[t], Wfs[k * 3 + 2], s2);
    }
    #pragma unroll
    for (int off = 16; off > 0; off >>= 1) {
        s0 += __shfl_down_sync(0xFFFFFFFFu, s0, off);
        s1 += __shfl_down_sync(0xFFFFFFFFu, s1, off);
        s2 += __shfl_down_sync(0xFFFFFFFFu, s2, off);
    }
    if (lane == 0) {
        out[(size_t)node * 3 + 0] = s0 + bf[0];
        out[(size_t)node * 3 + 1] = s1 + bf[1];
        out[(size_t)node * 3 + 2] = s2 + bf[2];
    }
}

// ---------------------------------------------------------------------------
extern "C" void kernel_launch(void* const* d_in, const int* in_sizes, int n_in,
                              void* d_out, int out_size)
{
    const float*      x_in = (const float*)d_in[0];
    const int*        ei   = (const int*)d_in[1];     // int32 (JAX x64 off)
    const float*      W1   = (const float*)d_in[2];   // [L, 2H, H]
    const float*      b1   = (const float*)d_in[3];   // [L, H]
    const float*      W2   = (const float*)d_in[4];   // [L, H, H]
    const float*      b2   = (const float*)d_in[5];   // [L, H]
    const float*      Wf   = (const float*)d_in[6];   // [H, 3]
    const float*      bf   = (const float*)d_in[7];   // [3]
    float*            out  = (float*)d_out;

    const int nN = in_sizes[0] / H;          // 50000
    const int nE = in_sizes[1] / 2;          // 800000
    const int L  = in_sizes[3] / H;          // 4

    void* base = nullptr;
    cudaGetSymbolAddress(&base, g_scratch4);
    float* X1 = (float*)base;
    float* X2 = X1 + NBUF;
    float* A  = X1 + 2 * NBUF;
    float* Bm = X1 + 3 * NBUF;

    cudaFuncSetAttribute(edge_mma_kernel, cudaFuncAttributeMaxDynamicSharedMemorySize, EDGE_SMEM);

    const int nodeBlocks = (nN + 31) / 32;
    const int edgeBlocks = 148 * 2;   // 2 blocks/SM (99KB smem each)
    float* bufs[2] = {X1, X2};

    const float* cur = x_in;
    for (int l = 0; l < L; l++) {
        node_gemm_kernel<<<nodeBlocks, 128>>>(cur, W1 + (size_t)l * 2 * H * H,
                                              b1 + (size_t)l * H, A, Bm, nN);
        float* y = bufs[l & 1];
        cudaMemsetAsync(y, 0xFF, (size_t)nN * H * sizeof(float), 0);  // NaN init
        edge_mma_kernel<<<edgeBlocks, EDGE_BLOCK, EDGE_SMEM>>>(
            A, Bm, W2 + (size_t)l * H * H, b2 + (size_t)l * H, ei, y, nE, nN);
        cur = y;
    }
    final_kernel<<<(nN + 7) / 8, 256>>>(cur, Wf, bf, out, nN);
}

// round 5
// speedup vs baseline: 1.1008x; 1.0001x over previous
#include <cuda_runtime.h>
#include <cuda_bf16.h>
#include <cstdint>

#define H 128
#define MAXN 50000
#define NBUF ((size_t)MAXN * H)

#define TILE_M 64
#define EDGE_BLOCK 128
#define HP 132   // padded smem pitch (words) -> conflict-free mma fragment loads
#define EDGE_SMEM ((128 * HP + TILE_M * HP + TILE_M) * 4)   // W2s + Hs + dstS ~ 99.3KB

// Scratch: X1, X2 (ping-pong node features), A, B (per-node partial GEMMs)
__device__ float4 g_scratch4[4 * NBUF / 4];

__device__ __forceinline__ void atomicMaxF(float* addr, float v) {
    if (v >= 0.f) atomicMax((int*)addr, __float_as_int(v));
    else          atomicMin((unsigned int*)addr, __float_as_uint(v));
}

__device__ __forceinline__ float tf32r(float x) {
    uint32_t u;
    asm("cvt.rna.tf32.f32 %0, %1;" : "=r"(u) : "f"(x));
    return __uint_as_float(u);
}

// ---------------------------------------------------------------------------
// Node GEMM: A[n] = x[n] @ (W1a - W1b) + b1 ;  B[n] = x[n] @ W1b   (fp32)
// ---------------------------------------------------------------------------
__global__ void __launch_bounds__(128) node_gemm_kernel(
    const float* __restrict__ x, const float* __restrict__ W1l,
    const float* __restrict__ b1l, float* __restrict__ A, float* __restrict__ Bm,
    int nN)
{
    __shared__ float xs[32][H];
    const int c = threadIdx.x;
    const int n0 = blockIdx.x * 32;

    #pragma unroll
    for (int n = 0; n < 32; n++) {
        int node = n0 + n;
        xs[n][c] = (node < nN) ? x[(size_t)node * H + c] : 0.f;
    }
    __syncthreads();

    float accA[32], accB[32];
    const float bias = b1l[c];
    #pragma unroll
    for (int n = 0; n < 32; n++) { accA[n] = bias; accB[n] = 0.f; }

    for (int k = 0; k < H; k++) {
        const float wa = W1l[k * H + c];
        const float wb = W1l[(H + k) * H + c];
        const float wd = wa - wb;
        #pragma unroll
        for (int n = 0; n < 32; n++) {
            const float xv = xs[n][k];
            accA[n] = fmaf(xv, wd, accA[n]);
            accB[n] = fmaf(xv, wb, accB[n]);
        }
    }

    #pragma unroll
    for (int n = 0; n < 32; n++) {
        int node = n0 + n;
        if (node < nN) {
            A [(size_t)node * H + c] = accA[n];
            Bm[(size_t)node * H + c] = accB[n];
        }
    }
}

// ---------------------------------------------------------------------------
// Edge kernel (tf32 tensor-core): tile of 64 edges.
//   Hs[m][k] = tf32(relu(A[dst]+B[src]));  out = Hs @ W2s (mma.sync m16n8k8)
//   y[dst] = max(y[dst], out + b2)  via racy-skip atomics.
// 4 warps tile 2(M)x2(N); warp tile M=32, N=64; K=128 in 16 k8-steps.
// ---------------------------------------------------------------------------
__global__ void __launch_bounds__(EDGE_BLOCK) edge_mma_kernel(
    const float* __restrict__ A, const float* __restrict__ Bm,
    const float* __restrict__ W2, const float* __restrict__ b2,
    const int* __restrict__ ei, float* __restrict__ y,
    int nE, int nN)
{
    extern __shared__ float sm[];
    float* W2s  = sm;                       // [128][HP]
    float* Hs   = sm + 128 * HP;            // [TILE_M][HP]
    int*   dstS = (int*)(sm + 128 * HP + TILE_M * HP);

    const int tid  = threadIdx.x;
    const int lane = tid & 31;
    const int wid  = tid >> 5;
    const int mg   = wid >> 1;      // 0..1 : M group (rows 32*mg..)
    const int ng   = wid & 1;       // 0..1 : N group (cols 64*ng..)
    const int lr   = lane >> 2;     // 0..7
    const int lc   = lane & 3;      // 0..3

    // Load W2 -> smem, tf32-rounded
    for (int i = tid; i < 128 * 32; i += EDGE_BLOCK) {
        const int k = i >> 5, j = i & 31;
        float4 w = *(const float4*)(W2 + k * H + j * 4);
        w.x = tf32r(w.x); w.y = tf32r(w.y); w.z = tf32r(w.z); w.w = tf32r(w.w);
        *(float4*)(W2s + k * HP + j * 4) = w;
    }

    // Bias pairs for my output columns
    float2 b2c[8];
    #pragma unroll
    for (int ni = 0; ni < 8; ni++) {
        const int col = 64 * ng + 8 * ni + 2 * lc;
        b2c[ni] = *(const float2*)(b2 + col);
    }
    __syncthreads();

    const int nwork  = nE + nN;
    const int ntiles = (nwork + TILE_M - 1) / TILE_M;

    for (int tile = blockIdx.x; tile < ntiles; tile += gridDim.x) {
        const int e0 = tile * TILE_M;

        // ---- build H tile: each thread = half a row (64 cols) ----
        {
            const int eL   = tid >> 1;
            const int half = tid & 1;
            const int e    = e0 + eL;
            int s = -1, d = -1;
            if (e < nE)         { s = ei[e]; d = ei[nE + e]; }
            else if (e < nwork) { s = d = e - nE; }   // self loop
            if (half == 0) dstS[eL] = d;

            float* hrow = Hs + eL * HP + half * 64;
            if (d >= 0) {
                const float4* ap = (const float4*)(A  + (size_t)d * H + half * 64);
                const float4* bp = (const float4*)(Bm + (size_t)s * H + half * 64);
                #pragma unroll
                for (int i = 0; i < 16; i++) {
                    const float4 a = ap[i], b = bp[i];
                    float4 h;
                    h.x = tf32r(fmaxf(a.x + b.x, 0.f));
                    h.y = tf32r(fmaxf(a.y + b.y, 0.f));
                    h.z = tf32r(fmaxf(a.z + b.z, 0.f));
                    h.w = tf32r(fmaxf(a.w + b.w, 0.f));
                    *(float4*)(hrow + i * 4) = h;
                }
            } else {
                #pragma unroll
                for (int i = 0; i < 16; i++)
                    *(float4*)(hrow + i * 4) = make_float4(0.f, 0.f, 0.f, 0.f);
            }
        }
        __syncthreads();

        // ---- mma: acc[mi][ni][c] over K=128 ----
        float acc[2][8][4];
        #pragma unroll
        for (int mi = 0; mi < 2; mi++)
            #pragma unroll
            for (int ni = 0; ni < 8; ni++)
                #pragma unroll
                for (int c = 0; c < 4; c++) acc[mi][ni][c] = 0.f;

        #pragma unroll
        for (int ks = 0; ks < 16; ks++) {
            const int kb = ks * 8;
            uint32_t a[2][4];
            #pragma unroll
            for (int mi = 0; mi < 2; mi++) {
                const float* ab = Hs + (32 * mg + 16 * mi + lr) * HP + kb + lc;
                a[mi][0] = __float_as_uint(ab[0]);
                a[mi][1] = __float_as_uint(ab[8 * HP]);
                a[mi][2] = __float_as_uint(ab[4]);
                a[mi][3] = __float_as_uint(ab[8 * HP + 4]);
            }
            #pragma unroll
            for (int ni = 0; ni < 8; ni++) {
                const float* bb = W2s + (kb + lc) * HP + 64 * ng + 8 * ni + lr;
                const uint32_t b0 = __float_as_uint(bb[0]);
                const uint32_t b1 = __float_as_uint(bb[4 * HP]);
                #pragma unroll
                for (int mi = 0; mi < 2; mi++) {
                    asm("mma.sync.aligned.m16n8k8.row.col.f32.tf32.tf32.f32 "
                        "{%0,%1,%2,%3}, {%4,%5,%6,%7}, {%8,%9}, {%0,%1,%2,%3};"
                        : "+f"(acc[mi][ni][0]), "+f"(acc[mi][ni][1]),
                          "+f"(acc[mi][ni][2]), "+f"(acc[mi][ni][3])
                        : "r"(a[mi][0]), "r"(a[mi][1]), "r"(a[mi][2]), "r"(a[mi][3]),
                          "r"(b0), "r"(b1));
                }
            }
        }

        // ---- output: atomicMax into y[dst] with racy skip ----
        #pragma unroll
        for (int mi = 0; mi < 2; mi++) {
            const int r0 = 32 * mg + 16 * mi + lr;
            const int d0 = dstS[r0];
            const int d1 = dstS[r0 + 8];
            #pragma unroll
            for (int ni = 0; ni < 8; ni++) {
                const int col = 64 * ng + 8 * ni + 2 * lc;
                if (d0 >= 0) {
                    float* yr = y + (size_t)d0 * H + col;
                    const float2 cur = *(const float2*)yr;
                    const float v0 = acc[mi][ni][0] + b2c[ni].x;
                    const float v1 = acc[mi][ni][1] + b2c[ni].y;
                    if (!(cur.x >= v0)) atomicMaxF(yr + 0, v0);
                    if (!(cur.y >= v1)) atomicMaxF(yr + 1, v1);
                }
                if (d1 >= 0) {
                    float* yr = y + (size_t)d1 * H + col;
                    const float2 cur = *(const float2*)yr;
                    const float v2 = acc[mi][ni][2] + b2c[ni].x;
                    const float v3 = acc[mi][ni][3] + b2c[ni].y;
                    if (!(cur.x >= v2)) atomicMaxF(yr + 0, v2);
                    if (!(cur.y >= v3)) atomicMaxF(yr + 1, v3);
                }
            }
        }
        __syncthreads();   // Hs/dstS stable until all warps finish this tile
    }
}

// ---------------------------------------------------------------------------
// Final: out[n] = x[n] @ Wf + bf   (H=128 -> D=3). Warp per node.
// ---------------------------------------------------------------------------
__global__ void __launch_bounds__(256) final_kernel(
    const float* __restrict__ x, const float* __restrict__ Wf,
    const float* __restrict__ bf, float* __restrict__ out, int nN)
{
    __shared__ float Wfs[H * 3];
    const int tid = threadIdx.x;
    for (int i = tid; i < H * 3; i += 256) Wfs[i] = Wf[i];
    __syncthreads();

    const int lane = tid & 31;
    const int node = blockIdx.x * 8 + (tid >> 5);
    if (node >= nN) return;

    const float4 xv = *(const float4*)(x + (size_t)node * H + lane * 4);
    float s0 = 0.f, s1 = 0.f, s2 = 0.f;
    const float xt[4] = {xv.x, xv.y, xv.z, xv.w};
    #pragma unroll
    for (int t = 0; t < 4; t++) {
        const int k = lane * 4 + t;
        s0 = fmaf(xt[t], Wfs[k * 3 + 0], s0);
        s1 = fmaf(xt[t], Wfs[k * 3 + 1], s1);
        s2 = fmaf(xt[t], Wfs[k * 3 + 2], s2);
    }
    #pragma unroll
    for (int off = 16; off > 0; off >>= 1) {
        s0 += __shfl_down_sync(0xFFFFFFFFu, s0, off);
        s1 += __shfl_down_sync(0xFFFFFFFFu, s1, off);
        s2 += __shfl_down_sync(0xFFFFFFFFu, s2, off);
    }
    if (lane == 0) {
        out[(size_t)node * 3 + 0] = s0 + bf[0];
        out[(size_t)node * 3 + 1] = s1 + bf[1];
        out[(size_t)node * 3 + 2] = s2 + bf[2];
    }
}

// ---------------------------------------------------------------------------
extern "C" void kernel_launch(void* const* d_in, const int* in_sizes, int n_in,
                              void* d_out, int out_size)
{
    const float*      x_in = (const float*)d_in[0];
    const int*        ei   = (const int*)d_in[1];     // int32 (JAX x64 off)
    const float*      W1   = (const float*)d_in[2];   // [L, 2H, H]
    const float*      b1   = (const float*)d_in[3];   // [L, H]
    const float*      W2   = (const float*)d_in[4];   // [L, H, H]
    const float*      b2   = (const float*)d_in[5];   // [L, H]
    const float*      Wf   = (const float*)d_in[6];   // [H, 3]
    const float*      bf   = (const float*)d_in[7];   // [3]
    float*            out  = (float*)d_out;

    const int nN = in_sizes[0] / H;          // 50000
    const int nE = in_sizes[1] / 2;          // 800000
    const int L  = in_sizes[3] / H;          // 4

    void* base = nullptr;
    cudaGetSymbolAddress(&base, g_scratch4);
    float* X1 = (float*)base;
    float* X2 = X1 + NBUF;
    float* A  = X1 + 2 * NBUF;
    float* Bm = X1 + 3 * NBUF;

    cudaFuncSetAttribute(edge_mma_kernel, cudaFuncAttributeMaxDynamicSharedMemorySize, EDGE_SMEM);

    const int nodeBlocks = (nN + 31) / 32;
    const int edgeBlocks = 148 * 2;   // 2 blocks/SM (99KB smem each)
    float* bufs[2] = {X1, X2};

    const float* cur = x_in;
    for (int l = 0; l < L; l++) {
        node_gemm_kernel<<<nodeBlocks, 128>>>(cur, W1 + (size_t)l * 2 * H * H,
                                              b1 + (size_t)l * H, A, Bm, nN);
        float* y = bufs[l & 1];
        cudaMemsetAsync(y, 0xFF, (size_t)nN * H * sizeof(float), 0);  // NaN init
        edge_mma_kernel<<<edgeBlocks, EDGE_BLOCK, EDGE_SMEM>>>(
            A, Bm, W2 + (size_t)l * H * H, b2 + (size_t)l * H, ei, y, nE, nN);
        cur = y;
    }
    final_kernel<<<(nN + 7) / 8, 256>>>(cur, Wf, bf, out, nN);
}

// round 6
// speedup vs baseline: 2.2970x; 2.0866x over previous
#include <cuda_runtime.h>
#include <cuda_bf16.h>
#include <cstdint>

#define H 128
#define MAXN 50000
#define NBUF ((size_t)MAXN * H)
#define MAXWORK 851968            // >= E + N

#define TILE_M 64
#define EDGE_BLOCK 128
#define HP 132   // padded smem pitch (words) -> conflict-free mma fragment loads
#define EDGE_SMEM ((128 * HP + TILE_M * HP + TILE_M) * 4)   // W2s + Hs + dstS ~ 99.3KB

// float scratch: X1, X2 (ping-pong), A, B (per-node partial GEMMs)
__device__ float4 g_scratch4[4 * NBUF / 4];
// int scratch: cnt[50048] | offs[50048] | sortedSrc[MAXWORK] | sortedDst[MAXWORK]
__device__ int g_iscratch[2 * 50048 + 2 * MAXWORK];

__device__ __forceinline__ void atomicMaxF(float* addr, float v) {
    if (v >= 0.f) atomicMax((int*)addr, __float_as_int(v));
    else          atomicMin((unsigned int*)addr, __float_as_uint(v));
}

__device__ __forceinline__ float tf32r(float x) {
    uint32_t u;
    asm("cvt.rna.tf32.f32 %0, %1;" : "=r"(u) : "f"(x));
    return __uint_as_float(u);
}

// ---------------------------------------------------------------------------
// Sorting (counting sort by dst). Runs once per launch, reused by all layers.
// ---------------------------------------------------------------------------
__global__ void hist_kernel(const int* __restrict__ ei, int* __restrict__ cnt,
                            int nE, int nN)
{
    const int nwork = nE + nN;
    for (int e = blockIdx.x * blockDim.x + threadIdx.x; e < nwork;
         e += gridDim.x * blockDim.x) {
        const int d = (e < nE) ? ei[nE + e] : (e - nE);
        atomicAdd(&cnt[d], 1);
    }
}

__global__ void __launch_bounds__(1024) scan_kernel(
    const int* __restrict__ cnt, int* __restrict__ offs, int nN)
{
    __shared__ int sums[1024];
    const int t = threadIdx.x;
    const int chunk = (nN + 1023) / 1024;
    const int lo = t * chunk;
    const int hi = min(lo + chunk, nN);
    int s = 0;
    for (int i = lo; i < hi; i++) s += cnt[i];
    sums[t] = s;
    __syncthreads();
    // inclusive Hillis-Steele
    for (int off = 1; off < 1024; off <<= 1) {
        int v = (t >= off) ? sums[t - off] : 0;
        __syncthreads();
        sums[t] += v;
        __syncthreads();
    }
    int run = sums[t] - s;   // exclusive prefix of this chunk
    for (int i = lo; i < hi; i++) {
        offs[i] = run;
        run += cnt[i];
    }
}

__global__ void scatter_kernel(const int* __restrict__ ei, int* __restrict__ offs,
                               int* __restrict__ sSrc, int* __restrict__ sDst,
                               int nE, int nN)
{
    const int nwork = nE + nN;
    for (int e = blockIdx.x * blockDim.x + threadIdx.x; e < nwork;
         e += gridDim.x * blockDim.x) {
        int s, d;
        if (e < nE) { s = ei[e]; d = ei[nE + e]; }
        else        { s = d = e - nE; }          // self loop
        const int pos = atomicAdd(&offs[d], 1);
        sSrc[pos] = s;
        sDst[pos] = d;
    }
}

// ---------------------------------------------------------------------------
// Node GEMM: A[n] = x[n] @ (W1a - W1b) + b1 ;  B[n] = x[n] @ W1b   (fp32)
// ---------------------------------------------------------------------------
__global__ void __launch_bounds__(128) node_gemm_kernel(
    const float* __restrict__ x, const float* __restrict__ W1l,
    const float* __restrict__ b1l, float* __restrict__ A, float* __restrict__ Bm,
    int nN)
{
    __shared__ float xs[32][H];
    const int c = threadIdx.x;
    const int n0 = blockIdx.x * 32;

    #pragma unroll
    for (int n = 0; n < 32; n++) {
        int node = n0 + n;
        xs[n][c] = (node < nN) ? x[(size_t)node * H + c] : 0.f;
    }
    __syncthreads();

    float accA[32], accB[32];
    const float bias = b1l[c];
    #pragma unroll
    for (int n = 0; n < 32; n++) { accA[n] = bias; accB[n] = 0.f; }

    for (int k = 0; k < H; k++) {
        const float wa = W1l[k * H + c];
        const float wb = W1l[(H + k) * H + c];
        const float wd = wa - wb;
        #pragma unroll
        for (int n = 0; n < 32; n++) {
            const float xv = xs[n][k];
            accA[n] = fmaf(xv, wd, accA[n]);
            accB[n] = fmaf(xv, wb, accB[n]);
        }
    }

    #pragma unroll
    for (int n = 0; n < 32; n++) {
        int node = n0 + n;
        if (node < nN) {
            A [(size_t)node * H + c] = accA[n];
            Bm[(size_t)node * H + c] = accB[n];
        }
    }
}

// ---------------------------------------------------------------------------
// Edge kernel (tf32 mma, dst-sorted edges): tile of 64 consecutive sorted edges.
//   Hs = tf32(relu(A[dst]+B[src]));  acc = Hs @ W2s (m16n8k8)
//   acc+b2 -> smem; column-parallel segmented max over sorted dst runs;
//   one atomicMaxF per (segment, col).
// ---------------------------------------------------------------------------
__global__ void __launch_bounds__(EDGE_BLOCK) edge_mma_kernel(
    const float* __restrict__ A, const float* __restrict__ Bm,
    const float* __restrict__ W2, const float* __restrict__ b2,
    const int* __restrict__ sSrc, const int* __restrict__ sDst,
    float* __restrict__ y, int nwork)
{
    extern __shared__ float sm[];
    float* W2s  = sm;                       // [128][HP]
    float* Hs   = sm + 128 * HP;            // [TILE_M][HP]  (reused as output tile)
    int*   dstS = (int*)(sm + 128 * HP + TILE_M * HP);

    const int tid  = threadIdx.x;
    const int lane = tid & 31;
    const int wid  = tid >> 5;
    const int mg   = wid >> 1;      // 0..1 : M group
    const int ng   = wid & 1;       // 0..1 : N group
    const int lr   = lane >> 2;     // 0..7
    const int lc   = lane & 3;      // 0..3

    // Load W2 -> smem, tf32-rounded
    for (int i = tid; i < 128 * 32; i += EDGE_BLOCK) {
        const int k = i >> 5, j = i & 31;
        float4 w = *(const float4*)(W2 + k * H + j * 4);
        w.x = tf32r(w.x); w.y = tf32r(w.y); w.z = tf32r(w.z); w.w = tf32r(w.w);
        *(float4*)(W2s + k * HP + j * 4) = w;
    }

    float2 b2c[8];
    #pragma unroll
    for (int ni = 0; ni < 8; ni++)
        b2c[ni] = *(const float2*)(b2 + 64 * ng + 8 * ni + 2 * lc);
    __syncthreads();

    const int ntiles = (nwork + TILE_M - 1) / TILE_M;

    for (int tile = blockIdx.x; tile < ntiles; tile += gridDim.x) {
        const int e0 = tile * TILE_M;

        // ---- build H tile: each thread = half a row (64 cols) ----
        {
            const int eL   = tid >> 1;
            const int half = tid & 1;
            const int e    = e0 + eL;
            int s = -1, d = -1;
            if (e < nwork) { s = sSrc[e]; d = sDst[e]; }
            if (half == 0) dstS[eL] = d;

            float* hrow = Hs + eL * HP + half * 64;
            if (d >= 0) {
                const float4* ap = (const float4*)(A  + (size_t)d * H + half * 64);
                const float4* bp = (const float4*)(Bm + (size_t)s * H + half * 64);
                #pragma unroll
                for (int i = 0; i < 16; i++) {
                    const float4 a = ap[i], b = bp[i];
                    float4 h;
                    h.x = tf32r(fmaxf(a.x + b.x, 0.f));
                    h.y = tf32r(fmaxf(a.y + b.y, 0.f));
                    h.z = tf32r(fmaxf(a.z + b.z, 0.f));
                    h.w = tf32r(fmaxf(a.w + b.w, 0.f));
                    *(float4*)(hrow + i * 4) = h;
                }
            } else {
                #pragma unroll
                for (int i = 0; i < 16; i++)
                    *(float4*)(hrow + i * 4) = make_float4(0.f, 0.f, 0.f, 0.f);
            }
        }
        __syncthreads();

        // ---- mma over K=128 ----
        float acc[2][8][4];
        #pragma unroll
        for (int mi = 0; mi < 2; mi++)
            #pragma unroll
            for (int ni = 0; ni < 8; ni++)
                #pragma unroll
                for (int c = 0; c < 4; c++) acc[mi][ni][c] = 0.f;

        #pragma unroll
        for (int ks = 0; ks < 16; ks++) {
            const int kb = ks * 8;
            uint32_t a[2][4];
            #pragma unroll
            for (int mi = 0; mi < 2; mi++) {
                const float* ab = Hs + (32 * mg + 16 * mi + lr) * HP + kb + lc;
                a[mi][0] = __float_as_uint(ab[0]);
                a[mi][1] = __float_as_uint(ab[8 * HP]);
                a[mi][2] = __float_as_uint(ab[4]);
                a[mi][3] = __float_as_uint(ab[8 * HP + 4]);
            }
            #pragma unroll
            for (int ni = 0; ni < 8; ni++) {
                const float* bb = W2s + (kb + lc) * HP + 64 * ng + 8 * ni + lr;
                const uint32_t b0 = __float_as_uint(bb[0]);
                const uint32_t b1 = __float_as_uint(bb[4 * HP]);
                #pragma unroll
                for (int mi = 0; mi < 2; mi++) {
                    asm("mma.sync.aligned.m16n8k8.row.col.f32.tf32.tf32.f32 "
                        "{%0,%1,%2,%3}, {%4,%5,%6,%7}, {%8,%9}, {%0,%1,%2,%3};"
                        : "+f"(acc[mi][ni][0]), "+f"(acc[mi][ni][1]),
                          "+f"(acc[mi][ni][2]), "+f"(acc[mi][ni][3])
                        : "r"(a[mi][0]), "r"(a[mi][1]), "r"(a[mi][2]), "r"(a[mi][3]),
                          "r"(b0), "r"(b1));
                }
            }
        }
        __syncthreads();   // all frag reads done before Hs is overwritten

        // ---- write acc+b2 back into Hs as the output tile [64][H] ----
        #pragma unroll
        for (int mi = 0; mi < 2; mi++) {
            const int r0  = 32 * mg + 16 * mi + lr;
            #pragma unroll
            for (int ni = 0; ni < 8; ni++) {
                const int col = 64 * ng + 8 * ni + 2 * lc;
                *(float2*)(Hs + r0 * HP + col) =
                    make_float2(acc[mi][ni][0] + b2c[ni].x, acc[mi][ni][1] + b2c[ni].y);
                *(float2*)(Hs + (r0 + 8) * HP + col) =
                    make_float2(acc[mi][ni][2] + b2c[ni].x, acc[mi][ni][3] + b2c[ni].y);
            }
        }
        __syncthreads();

        // ---- column-parallel segmented max over sorted dst runs ----
        {
            const int c = tid;          // one column per thread (H == EDGE_BLOCK)
            int cur_d = -1;
            float m = 0.f;
            #pragma unroll 4
            for (int r = 0; r < TILE_M; r++) {
                const int d   = dstS[r];          // broadcast
                const float v = Hs[r * HP + c];
                if (d != cur_d) {
                    if (cur_d >= 0) atomicMaxF(y + (size_t)cur_d * H + c, m);
                    cur_d = d;
                    m = v;
                } else {
                    m = fmaxf(m, v);
                }
            }
            if (cur_d >= 0) atomicMaxF(y + (size_t)cur_d * H + c, m);
        }
        __syncthreads();   // tile fully consumed before next build
    }
}

// ---------------------------------------------------------------------------
// Final: out[n] = x[n] @ Wf + bf   (H=128 -> D=3). Warp per node.
// ---------------------------------------------------------------------------
__global__ void __launch_bounds__(256) final_kernel(
    const float* __restrict__ x, const float* __restrict__ Wf,
    const float* __restrict__ bf, float* __restrict__ out, int nN)
{
    __shared__ float Wfs[H * 3];
    const int tid = threadIdx.x;
    for (int i = tid; i < H * 3; i += 256) Wfs[i] = Wf[i];
    __syncthreads();

    const int lane = tid & 31;
    const int node = blockIdx.x * 8 + (tid >> 5);
    if (node >= nN) return;

    const float4 xv = *(const float4*)(x + (size_t)node * H + lane * 4);
    float s0 = 0.f, s1 = 0.f, s2 = 0.f;
    const float xt[4] = {xv.x, xv.y, xv.z, xv.w};
    #pragma unroll
    for (int t = 0; t < 4; t++) {
        const int k = lane * 4 + t;
        s0 = fmaf(xt[t], Wfs[k * 3 + 0], s0);
        s1 = fmaf(xt[t], Wfs[k * 3 + 1], s1);
        s2 = fmaf(xt[t], Wfs[k * 3 + 2], s2);
    }
    #pragma unroll
    for (int off = 16; off > 0; off >>= 1) {
        s0 += __shfl_down_sync(0xFFFFFFFFu, s0, off);
        s1 += __shfl_down_sync(0xFFFFFFFFu, s1, off);
        s2 += __shfl_down_sync(0xFFFFFFFFu, s2, off);
    }
    if (lane == 0) {
        out[(size_t)node * 3 + 0] = s0 + bf[0];
        out[(size_t)node * 3 + 1] = s1 + bf[1];
        out[(size_t)node * 3 + 2] = s2 + bf[2];
    }
}

// ---------------------------------------------------------------------------
extern "C" void kernel_launch(void* const* d_in, const int* in_sizes, int n_in,
                              void* d_out, int out_size)
{
    const float*      x_in = (const float*)d_in[0];
    const int*        ei   = (const int*)d_in[1];     // int32 (JAX x64 off)
    const float*      W1   = (const float*)d_in[2];   // [L, 2H, H]
    const float*      b1   = (const float*)d_in[3];   // [L, H]
    const float*      W2   = (const float*)d_in[4];   // [L, H, H]
    const float*      b2   = (const float*)d_in[5];   // [L, H]
    const float*      Wf   = (const float*)d_in[6];   // [H, 3]
    const float*      bf   = (const float*)d_in[7];   // [3]
    float*            out  = (float*)d_out;

    const int nN = in_sizes[0] / H;          // 50000
    const int nE = in_sizes[1] / 2;          // 800000
    const int L  = in_sizes[3] / H;          // 4
    const int nwork = nE + nN;

    void* base = nullptr;
    cudaGetSymbolAddress(&base, g_scratch4);
    float* X1 = (float*)base;
    float* X2 = X1 + NBUF;
    float* A  = X1 + 2 * NBUF;
    float* Bm = X1 + 3 * NBUF;

    void* ibase = nullptr;
    cudaGetSymbolAddress(&ibase, g_iscratch);
    int* cnt  = (int*)ibase;
    int* offs = cnt + 50048;
    int* sSrc = cnt + 2 * 50048;
    int* sDst = sSrc + MAXWORK;

    cudaFuncSetAttribute(edge_mma_kernel, cudaFuncAttributeMaxDynamicSharedMemorySize, EDGE_SMEM);

    // ---- sort edges by dst (once; reused by all layers) ----
    cudaMemsetAsync(cnt, 0, 50048 * sizeof(int), 0);
    hist_kernel<<<592, 256>>>(ei, cnt, nE, nN);
    scan_kernel<<<1, 1024>>>(cnt, offs, nN);
    scatter_kernel<<<592, 256>>>(ei, offs, sSrc, sDst, nE, nN);

    const int nodeBlocks = (nN + 31) / 32;
    const int edgeBlocks = 148 * 2;   // 2 blocks/SM (99KB smem each)
    float* bufs[2] = {X1, X2};

    const float* cur = x_in;
    for (int l = 0; l < L; l++) {
        node_gemm_kernel<<<nodeBlocks, 128>>>(cur, W1 + (size_t)l * 2 * H * H,
                                              b1 + (size_t)l * H, A, Bm, nN);
        float* y = bufs[l & 1];
        cudaMemsetAsync(y, 0xFF, (size_t)nN * H * sizeof(float), 0);  // NaN init
        edge_mma_kernel<<<edgeBlocks, EDGE_BLOCK, EDGE_SMEM>>>(
            A, Bm, W2 + (size_t)l * H * H, b2 + (size_t)l * H, sSrc, sDst, y, nwork);
        cur = y;
    }
    final_kernel<<<(nN + 7) / 8, 256>>>(cur, Wf, bf, out, nN);
}

// round 7
// speedup vs baseline: 2.5642x; 1.1163x over previous
#include <cuda_runtime.h>
#include <cuda_bf16.h>
#include <cstdint>

#define H 128
#define MAXN 50000
#define NBUF ((size_t)MAXN * H)
#define MAXWORK 851968            // >= E + N

#define TILE_M 64
#define EDGE_BLOCK 128
#define HP 132   // padded smem pitch (words) -> conflict-free mma fragment loads
#define EDGE_SMEM ((128 * HP + TILE_M * HP + TILE_M) * 4)   // W2s + Hs + dstS ~ 99.3KB
#define NODE_SMEM ((2 * 128 * HP + 2 * 64 * HP) * 4)        // Wh,Wl,Xh,Xl ~ 198KB

// float scratch: X1, X2 (ping-pong), A, B (per-node partial GEMMs)
__device__ float4 g_scratch4[4 * NBUF / 4];
// int scratch: cnt[50048] | offs[50048] | sortedSrc[MAXWORK] | sortedDst[MAXWORK]
__device__ int g_iscratch[2 * 50048 + 2 * MAXWORK];

__device__ __forceinline__ void atomicMaxF(float* addr, float v) {
    if (v >= 0.f) atomicMax((int*)addr, __float_as_int(v));
    else          atomicMin((unsigned int*)addr, __float_as_uint(v));
}

__device__ __forceinline__ float tf32r(float x) {
    uint32_t u;
    asm("cvt.rna.tf32.f32 %0, %1;" : "=r"(u) : "f"(x));
    return __uint_as_float(u);
}

#define MMA_TF32(acc, a0, a1, a2, a3, b0, b1)                                   \
    asm("mma.sync.aligned.m16n8k8.row.col.f32.tf32.tf32.f32 "                   \
        "{%0,%1,%2,%3}, {%4,%5,%6,%7}, {%8,%9}, {%0,%1,%2,%3};"                 \
        : "+f"(acc[0]), "+f"(acc[1]), "+f"(acc[2]), "+f"(acc[3])                \
        : "r"(a0), "r"(a1), "r"(a2), "r"(a3), "r"(b0), "r"(b1))

// ---------------------------------------------------------------------------
// Sorting (counting sort by dst). Runs once per launch, reused by all layers.
// ---------------------------------------------------------------------------
__global__ void hist_kernel(const int* __restrict__ ei, int* __restrict__ cnt,
                            int nE, int nN)
{
    const int nwork = nE + nN;
    for (int e = blockIdx.x * blockDim.x + threadIdx.x; e < nwork;
         e += gridDim.x * blockDim.x) {
        const int d = (e < nE) ? ei[nE + e] : (e - nE);
        atomicAdd(&cnt[d], 1);
    }
}

__global__ void __launch_bounds__(1024) scan_kernel(
    const int* __restrict__ cnt, int* __restrict__ offs, int nN)
{
    __shared__ int sums[1024];
    const int t = threadIdx.x;
    const int chunk = (nN + 1023) / 1024;
    const int lo = t * chunk;
    const int hi = min(lo + chunk, nN);
    int s = 0;
    for (int i = lo; i < hi; i++) s += cnt[i];
    sums[t] = s;
    __syncthreads();
    for (int off = 1; off < 1024; off <<= 1) {
        int v = (t >= off) ? sums[t - off] : 0;
        __syncthreads();
        sums[t] += v;
        __syncthreads();
    }
    int run = sums[t] - s;   // exclusive prefix
    for (int i = lo; i < hi; i++) {
        offs[i] = run;
        run += cnt[i];
    }
}

__global__ void scatter_kernel(const int* __restrict__ ei, int* __restrict__ offs,
                               int* __restrict__ sSrc, int* __restrict__ sDst,
                               int nE, int nN)
{
    const int nwork = nE + nN;
    for (int e = blockIdx.x * blockDim.x + threadIdx.x; e < nwork;
         e += gridDim.x * blockDim.x) {
        int s, d;
        if (e < nE) { s = ei[e]; d = ei[nE + e]; }
        else        { s = d = e - nE; }
        const int pos = atomicAdd(&offs[d], 1);
        sSrc[pos] = s;
        sDst[pos] = d;
    }
}

// ---------------------------------------------------------------------------
// Node GEMM via tensor cores, 3xTF32 split (fp32-accurate).
// blockIdx.y==0: out = x @ (W1a - W1b) + b1 -> A
// blockIdx.y==1: out = x @ W1b              -> Bm
// 256 threads = 8 warps, warp grid 2(M)x4(N); warp tile M=32,N=32; K=128.
// ---------------------------------------------------------------------------
__global__ void __launch_bounds__(256) node_mma_kernel(
    const float* __restrict__ x, const float* __restrict__ W1l,
    const float* __restrict__ b1l, float* __restrict__ A, float* __restrict__ Bm,
    int nN)
{
    extern __shared__ float sm[];
    float* Wh = sm;                  // [128][HP]
    float* Wl = sm + 128 * HP;       // [128][HP]
    float* Xh = sm + 2 * 128 * HP;   // [64][HP]
    float* Xl = Xh + 64 * HP;        // [64][HP]

    const int tid  = threadIdx.x;
    const int lane = tid & 31;
    const int wid  = tid >> 5;
    const int mg   = wid >> 2;      // 0..1
    const int ng   = wid & 3;       // 0..3
    const int lr   = lane >> 2;     // 0..7
    const int lc   = lane & 3;      // 0..3
    const int half = blockIdx.y;

    // Load effective weights, split hi/lo
    for (int i = tid; i < 128 * 128; i += 256) {
        const int k = i >> 7, j = i & 127;
        float wv = (half == 0)
            ? (W1l[k * H + j] - W1l[(H + k) * H + j])
            : W1l[(H + k) * H + j];
        const float hi = tf32r(wv);
        Wh[k * HP + j] = hi;
        Wl[k * HP + j] = tf32r(wv - hi);
    }

    float2 b1c[4];
    #pragma unroll
    for (int ni = 0; ni < 4; ni++) {
        if (half == 0) b1c[ni] = *(const float2*)(b1l + 32 * ng + 8 * ni + 2 * lc);
        else           b1c[ni] = make_float2(0.f, 0.f);
    }
    float* outP = (half == 0) ? A : Bm;
    __syncthreads();

    const int ntiles = (nN + 63) / 64;
    for (int tile = blockIdx.x; tile < ntiles; tile += gridDim.x) {
        const int n0 = tile * 64;

        // load x tile (64x128), split hi/lo
        for (int i = tid; i < 64 * 32; i += 256) {
            const int r = i >> 5, j4 = (i & 31) * 4;
            float4 v = (n0 + r < nN)
                ? *(const float4*)(x + (size_t)(n0 + r) * H + j4)
                : make_float4(0.f, 0.f, 0.f, 0.f);
            float4 hi4, lo4;
            hi4.x = tf32r(v.x); lo4.x = tf32r(v.x - hi4.x);
            hi4.y = tf32r(v.y); lo4.y = tf32r(v.y - hi4.y);
            hi4.z = tf32r(v.z); lo4.z = tf32r(v.z - hi4.z);
            hi4.w = tf32r(v.w); lo4.w = tf32r(v.w - hi4.w);
            *(float4*)(Xh + r * HP + j4) = hi4;
            *(float4*)(Xl + r * HP + j4) = lo4;
        }
        __syncthreads();

        float acc[2][4][4];
        #pragma unroll
        for (int mi = 0; mi < 2; mi++)
            #pragma unroll
            for (int ni = 0; ni < 4; ni++)
                #pragma unroll
                for (int c = 0; c < 4; c++) acc[mi][ni][c] = 0.f;

        #pragma unroll
        for (int ks = 0; ks < 16; ks++) {
            const int kb = ks * 8;
            uint32_t ah[2][4], al[2][4];
            #pragma unroll
            for (int mi = 0; mi < 2; mi++) {
                const int ro = (32 * mg + 16 * mi + lr) * HP + kb + lc;
                ah[mi][0] = __float_as_uint(Xh[ro]);
                ah[mi][1] = __float_as_uint(Xh[ro + 8 * HP]);
                ah[mi][2] = __float_as_uint(Xh[ro + 4]);
                ah[mi][3] = __float_as_uint(Xh[ro + 8 * HP + 4]);
                al[mi][0] = __float_as_uint(Xl[ro]);
                al[mi][1] = __float_as_uint(Xl[ro + 8 * HP]);
                al[mi][2] = __float_as_uint(Xl[ro + 4]);
                al[mi][3] = __float_as_uint(Xl[ro + 8 * HP + 4]);
            }
            #pragma unroll
            for (int ni = 0; ni < 4; ni++) {
                const int bo = (kb + lc) * HP + 32 * ng + 8 * ni + lr;
                const uint32_t bh0 = __float_as_uint(Wh[bo]);
                const uint32_t bh1 = __float_as_uint(Wh[bo + 4 * HP]);
                const uint32_t bl0 = __float_as_uint(Wl[bo]);
                const uint32_t bl1 = __float_as_uint(Wl[bo + 4 * HP]);
                #pragma unroll
                for (int mi = 0; mi < 2; mi++) {
                    MMA_TF32(acc[mi][ni], ah[mi][0], ah[mi][1], ah[mi][2], ah[mi][3], bh0, bh1);
                    MMA_TF32(acc[mi][ni], al[mi][0], al[mi][1], al[mi][2], al[mi][3], bh0, bh1);
                    MMA_TF32(acc[mi][ni], ah[mi][0], ah[mi][1], ah[mi][2], ah[mi][3], bl0, bl1);
                }
            }
        }
        __syncthreads();   // frag reads done before Xh/Xl overwritten next tile

        #pragma unroll
        for (int mi = 0; mi < 2; mi++) {
            const int r0 = 32 * mg + 16 * mi + lr;
            #pragma unroll
            for (int ni = 0; ni < 4; ni++) {
                const int col = 32 * ng + 8 * ni + 2 * lc;
                if (n0 + r0 < nN)
                    *(float2*)(outP + (size_t)(n0 + r0) * H + col) =
                        make_float2(acc[mi][ni][0] + b1c[ni].x, acc[mi][ni][1] + b1c[ni].y);
                if (n0 + r0 + 8 < nN)
                    *(float2*)(outP + (size_t)(n0 + r0 + 8) * H + col) =
                        make_float2(acc[mi][ni][2] + b1c[ni].x, acc[mi][ni][3] + b1c[ni].y);
            }
        }
    }
}

// ---------------------------------------------------------------------------
// Edge kernel (tf32 mma, dst-sorted edges)
// ---------------------------------------------------------------------------
__global__ void __launch_bounds__(EDGE_BLOCK) edge_mma_kernel(
    const float* __restrict__ A, const float* __restrict__ Bm,
    const float* __restrict__ W2, const float* __restrict__ b2,
    const int* __restrict__ sSrc, const int* __restrict__ sDst,
    float* __restrict__ y, int nwork)
{
    extern __shared__ float sm[];
    float* W2s  = sm;                       // [128][HP]
    float* Hs   = sm + 128 * HP;            // [TILE_M][HP]
    int*   dstS = (int*)(sm + 128 * HP + TILE_M * HP);

    const int tid  = threadIdx.x;
    const int lane = tid & 31;
    const int wid  = tid >> 5;
    const int mg   = wid >> 1;
    const int ng   = wid & 1;
    const int lr   = lane >> 2;
    const int lc   = lane & 3;

    for (int i = tid; i < 128 * 32; i += EDGE_BLOCK) {
        const int k = i >> 5, j = i & 31;
        float4 w = *(const float4*)(W2 + k * H + j * 4);
        w.x = tf32r(w.x); w.y = tf32r(w.y); w.z = tf32r(w.z); w.w = tf32r(w.w);
        *(float4*)(W2s + k * HP + j * 4) = w;
    }

    float2 b2c[8];
    #pragma unroll
    for (int ni = 0; ni < 8; ni++)
        b2c[ni] = *(const float2*)(b2 + 64 * ng + 8 * ni + 2 * lc);
    __syncthreads();

    const int ntiles = (nwork + TILE_M - 1) / TILE_M;

    for (int tile = blockIdx.x; tile < ntiles; tile += gridDim.x) {
        const int e0 = tile * TILE_M;

        {
            const int eL   = tid >> 1;
            const int half = tid & 1;
            const int e    = e0 + eL;
            int s = -1, d = -1;
            if (e < nwork) { s = sSrc[e]; d = sDst[e]; }
            if (half == 0) dstS[eL] = d;

            float* hrow = Hs + eL * HP + half * 64;
            if (d >= 0) {
                const float4* ap = (const float4*)(A  + (size_t)d * H + half * 64);
                const float4* bp = (const float4*)(Bm + (size_t)s * H + half * 64);
                #pragma unroll
                for (int i = 0; i < 16; i++) {
                    const float4 a = ap[i], b = bp[i];
                    float4 h;
                    h.x = tf32r(fmaxf(a.x + b.x, 0.f));
                    h.y = tf32r(fmaxf(a.y + b.y, 0.f));
                    h.z = tf32r(fmaxf(a.z + b.z, 0.f));
                    h.w = tf32r(fmaxf(a.w + b.w, 0.f));
                    *(float4*)(hrow + i * 4) = h;
                }
            } else {
                #pragma unroll
                for (int i = 0; i < 16; i++)
                    *(float4*)(hrow + i * 4) = make_float4(0.f, 0.f, 0.f, 0.f);
            }
        }
        __syncthreads();

        float acc[2][8][4];
        #pragma unroll
        for (int mi = 0; mi < 2; mi++)
            #pragma unroll
            for (int ni = 0; ni < 8; ni++)
                #pragma unroll
                for (int c = 0; c < 4; c++) acc[mi][ni][c] = 0.f;

        #pragma unroll
        for (int ks = 0; ks < 16; ks++) {
            const int kb = ks * 8;
            uint32_t a[2][4];
            #pragma unroll
            for (int mi = 0; mi < 2; mi++) {
                const float* ab = Hs + (32 * mg + 16 * mi + lr) * HP + kb + lc;
                a[mi][0] = __float_as_uint(ab[0]);
                a[mi][1] = __float_as_uint(ab[8 * HP]);
                a[mi][2] = __float_as_uint(ab[4]);
                a[mi][3] = __float_as_uint(ab[8 * HP + 4]);
            }
            #pragma unroll
            for (int ni = 0; ni < 8; ni++) {
                const float* bb = W2s + (kb + lc) * HP + 64 * ng + 8 * ni + lr;
                const uint32_t b0 = __float_as_uint(bb[0]);
                const uint32_t b1 = __float_as_uint(bb[4 * HP]);
                #pragma unroll
                for (int mi = 0; mi < 2; mi++)
                    MMA_TF32(acc[mi][ni], a[mi][0], a[mi][1], a[mi][2], a[mi][3], b0, b1);
            }
        }
        __syncthreads();

        #pragma unroll
        for (int mi = 0; mi < 2; mi++) {
            const int r0  = 32 * mg + 16 * mi + lr;
            #pragma unroll
            for (int ni = 0; ni < 8; ni++) {
                const int col = 64 * ng + 8 * ni + 2 * lc;
                *(float2*)(Hs + r0 * HP + col) =
                    make_float2(acc[mi][ni][0] + b2c[ni].x, acc[mi][ni][1] + b2c[ni].y);
                *(float2*)(Hs + (r0 + 8) * HP + col) =
                    make_float2(acc[mi][ni][2] + b2c[ni].x, acc[mi][ni][3] + b2c[ni].y);
            }
        }
        __syncthreads();

        {
            const int c = tid;
            int cur_d = -1;
            float m = 0.f;
            #pragma unroll 4
            for (int r = 0; r < TILE_M; r++) {
                const int d   = dstS[r];
                const float v = Hs[r * HP + c];
                if (d != cur_d) {
                    if (cur_d >= 0) atomicMaxF(y + (size_t)cur_d * H + c, m);
                    cur_d = d;
                    m = v;
                } else {
                    m = fmaxf(m, v);
                }
            }
            if (cur_d >= 0) atomicMaxF(y + (size_t)cur_d * H + c, m);
        }
        __syncthreads();
    }
}

// ---------------------------------------------------------------------------
// Final: out[n] = x[n] @ Wf + bf   (H=128 -> D=3). Warp per node.
// ---------------------------------------------------------------------------
__global__ void __launch_bounds__(256) final_kernel(
    const float* __restrict__ x, const float* __restrict__ Wf,
    const float* __restrict__ bf, float* __restrict__ out, int nN)
{
    __shared__ float Wfs[H * 3];
    const int tid = threadIdx.x;
    for (int i = tid; i < H * 3; i += 256) Wfs[i] = Wf[i];
    __syncthreads();

    const int lane = tid & 31;
    const int node = blockIdx.x * 8 + (tid >> 5);
    if (node >= nN) return;

    const float4 xv = *(const float4*)(x + (size_t)node * H + lane * 4);
    float s0 = 0.f, s1 = 0.f, s2 = 0.f;
    const float xt[4] = {xv.x, xv.y, xv.z, xv.w};
    #pragma unroll
    for (int t = 0; t < 4; t++) {
        const int k = lane * 4 + t;
        s0 = fmaf(xt[t], Wfs[k * 3 + 0], s0);
        s1 = fmaf(xt[t], Wfs[k * 3 + 1], s1);
        s2 = fmaf(xt[t], Wfs[k * 3 + 2], s2);
    }
    #pragma unroll
    for (int off = 16; off > 0; off >>= 1) {
        s0 += __shfl_down_sync(0xFFFFFFFFu, s0, off);
        s1 += __shfl_down_sync(0xFFFFFFFFu, s1, off);
        s2 += __shfl_down_sync(0xFFFFFFFFu, s2, off);
    }
    if (lane == 0) {
        out[(size_t)node * 3 + 0] = s0 + bf[0];
        out[(size_t)node * 3 + 1] = s1 + bf[1];
        out[(size_t)node * 3 + 2] = s2 + bf[2];
    }
}

// ---------------------------------------------------------------------------
extern "C" void kernel_launch(void* const* d_in, const int* in_sizes, int n_in,
                              void* d_out, int out_size)
{
    const float*      x_in = (const float*)d_in[0];
    const int*        ei   = (const int*)d_in[1];
    const float*      W1   = (const float*)d_in[2];
    const float*      b1   = (const float*)d_in[3];
    const float*      W2   = (const float*)d_in[4];
    const float*      b2   = (const float*)d_in[5];
    const float*      Wf   = (const float*)d_in[6];
    const float*      bf   = (const float*)d_in[7];
    float*            out  = (float*)d_out;

    const int nN = in_sizes[0] / H;          // 50000
    const int nE = in_sizes[1] / 2;          // 800000
    const int L  = in_sizes[3] / H;          // 4
    const int nwork = nE + nN;

    void* base = nullptr;
    cudaGetSymbolAddress(&base, g_scratch4);
    float* X1 = (float*)base;
    float* X2 = X1 + NBUF;
    float* A  = X1 + 2 * NBUF;
    float* Bm = X1 + 3 * NBUF;

    void* ibase = nullptr;
    cudaGetSymbolAddress(&ibase, g_iscratch);
    int* cnt  = (int*)ibase;
    int* offs = cnt + 50048;
    int* sSrc = cnt + 2 * 50048;
    int* sDst = sSrc + MAXWORK;

    cudaFuncSetAttribute(edge_mma_kernel, cudaFuncAttributeMaxDynamicSharedMemorySize, EDGE_SMEM);
    cudaFuncSetAttribute(node_mma_kernel, cudaFuncAttributeMaxDynamicSharedMemorySize, NODE_SMEM);

    // ---- sort edges by dst (once; reused by all layers) ----
    cudaMemsetAsync(cnt, 0, 50048 * sizeof(int), 0);
    hist_kernel<<<592, 256>>>(ei, cnt, nE, nN);
    scan_kernel<<<1, 1024>>>(cnt, offs, nN);
    scatter_kernel<<<592, 256>>>(ei, offs, sSrc, sDst, nE, nN);

    const int edgeBlocks = 148 * 2;
    float* bufs[2] = {X1, X2};

    const float* cur = x_in;
    for (int l = 0; l < L; l++) {
        node_mma_kernel<<<dim3(74, 2), 256, NODE_SMEM>>>(
            cur, W1 + (size_t)l * 2 * H * H, b1 + (size_t)l * H, A, Bm, nN);
        float* y = bufs[l & 1];
        cudaMemsetAsync(y, 0xFF, (size_t)nN * H * sizeof(float), 0);  // NaN init
        edge_mma_kernel<<<edgeBlocks, EDGE_BLOCK, EDGE_SMEM>>>(
            A, Bm, W2 + (size_t)l * H * H, b2 + (size_t)l * H, sSrc, sDst, y, nwork);
        cur = y;
    }
    final_kernel<<<(nN + 7) / 8, 256>>>(cur, Wf, bf, out, nN);
}